// round 6
// baseline (speedup 1.0000x reference)
#include <cuda_runtime.h>
#include <cuda_bf16.h>

#define BN 8192
#define EN 8
#define HN 128
#define TS 128
#define NT (BN / TS)                 // 64 tiles per dim
#define NPAIR (NT * (NT + 1) / 2)    // 2080 upper-triangular tile pairs
#define GRID_PAIR 296                // 2 CTAs/SM, one wave
#define PREP_BLKS (BN / 8)           // 1024

// ---------------- device scratch -------------------------------------------
// bf16 tile images in 4 K-chunks of 32. Chunk layout: 128 rows x 64B, packed
// two rows per 128B line, 16B-chunk swizzle:
//   byte(r,q) = (r>>1)*128 + (((r&1)*4) | (q ^ ((r>>1)&3)))*16,  q in 0..3
__device__ __align__(1024) unsigned char g_ct[4][NT][TS * 64];  // 2 MB
__device__ __align__(16) float g_p[BN * EN];
__device__ __align__(16) float g_lp[BN * EN];
__device__ float g_a[BN];
// prep per-block partials (written unconditionally -> no zeroing kernel)
__device__ double g_pp_task[PREP_BLKS], g_pp_eff[PREP_BLKS], g_pp_ent[PREP_BLKS];
__device__ float  g_pp_us[PREP_BLKS * EN];
// pair per-CTA partials + never-reset ticket (modular check is replay-safe)
__device__ double g_pair_kl[GRID_PAIR];
__device__ double g_pair_cnt[GRID_PAIR];
__device__ unsigned g_ticket;

// ---------------- PTX helpers ----------------------------------------------
__device__ __forceinline__ unsigned smem_u32(const void* p) {
    unsigned a;
    asm("{ .reg .u64 t; cvta.to.shared.u64 t, %1; cvt.u32.u64 %0, t; }"
        : "=r"(a) : "l"(p));
    return a;
}
__device__ __forceinline__ void ldsm4(unsigned* r, unsigned addr) {
    asm volatile("ldmatrix.sync.aligned.m8n8.x4.shared.b16 {%0,%1,%2,%3}, [%4];"
                 : "=r"(r[0]), "=r"(r[1]), "=r"(r[2]), "=r"(r[3]) : "r"(addr));
}
__device__ __forceinline__ void mma16816(float* d, const unsigned* a, const unsigned* b) {
    asm volatile(
        "mma.sync.aligned.m16n8k16.row.col.f32.bf16.bf16.f32 "
        "{%0,%1,%2,%3}, {%4,%5,%6,%7}, {%8,%9}, {%0,%1,%2,%3};"
        : "+f"(d[0]), "+f"(d[1]), "+f"(d[2]), "+f"(d[3])
        : "r"(a[0]), "r"(a[1]), "r"(a[2]), "r"(a[3]), "r"(b[0]), "r"(b[1]));
}
__device__ __forceinline__ void cpa16(unsigned dst, const void* src) {
    asm volatile("cp.async.cg.shared.global [%0], [%1], 16;"
                 :: "r"(dst), "l"(src) : "memory");
}
#define CP_COMMIT() asm volatile("cp.async.commit_group;" ::: "memory")
#define CP_WAIT1()  asm volatile("cp.async.wait_group 1;" ::: "memory")
#define CP_WAIT0()  asm volatile("cp.async.wait_group 0;" ::: "memory")

// swizzled byte offset within a K-chunk tile
__device__ __forceinline__ unsigned coff(int r, int q) {
    return ((unsigned)(r >> 1) << 7) +
           ((((unsigned)(r & 1) << 2) | ((unsigned)q ^ ((unsigned)(r >> 1) & 3))) << 4);
}
__device__ __forceinline__ double wredd(double v) {
#pragma unroll
    for (int o = 16; o > 0; o >>= 1) v += __shfl_xor_sync(0xffffffffu, v, o);
    return v;
}

// ---------------- per-row preprocessing + cheap loss partials ---------------
__global__ __launch_bounds__(256) void prep_kernel(
    const float* __restrict__ logits,
    const int* __restrict__ targets,
    const float* __restrict__ rp,
    const float* __restrict__ emb) {
    int warp = threadIdx.x >> 5, lane = threadIdx.x & 31;
    int row = blockIdx.x * 8 + warp;
    __shared__ float  s_us[EN];
    __shared__ double s_task[8], s_eff[8], s_ent[8];
    if (threadIdx.x < EN) s_us[threadIdx.x] = 0.f;
    __syncthreads();

    // normalize embedding row (float4 per lane = 4 consecutive k-cols)
    float4 v = *(const float4*)(emb + (size_t)row * HN + lane * 4);
    float ss = v.x * v.x + v.y * v.y + v.z * v.z + v.w * v.w;
#pragma unroll
    for (int o = 16; o > 0; o >>= 1) ss += __shfl_xor_sync(0xffffffffu, ss, o);
    float inv = rsqrtf(ss);
    float4 w = make_float4(v.x * inv, v.y * inv, v.z * inv, v.w * inv);

    // store bf16 into chunked swizzled tile image
    {
        int cc = lane >> 3;                  // K-chunk 0..3
        int q  = (lane & 7) >> 1;            // 16B chunk in row
        int lr = row & (TS - 1);
        unsigned off = coff(lr, q) + (unsigned)(lane & 1) * 8;
        unsigned u0 = __bfloat16_as_ushort(__float2bfloat16_rn(w.x));
        unsigned u1 = __bfloat16_as_ushort(__float2bfloat16_rn(w.y));
        unsigned u2 = __bfloat16_as_ushort(__float2bfloat16_rn(w.z));
        unsigned u3 = __bfloat16_as_ushort(__float2bfloat16_rn(w.w));
        uint2 val = make_uint2(u0 | (u1 << 16), u2 | (u3 << 16));
        *(uint2*)(&g_ct[cc][row >> 7][off]) = val;
    }

    // routing-prob softmax over E=8
    float r = (lane < EN) ? rp[row * EN + lane] : -3.0e38f;
    float m = r;
#pragma unroll
    for (int o = 4; o > 0; o >>= 1) m = fmaxf(m, __shfl_xor_sync(0xffffffffu, m, o));
    float ex = (lane < EN) ? expf(r - m) : 0.f;
    float es = ex;
#pragma unroll
    for (int o = 4; o > 0; o >>= 1) es += __shfl_xor_sync(0xffffffffu, es, o);
    float lse = m + logf(es);
    float lp = r - lse;
    float p  = expf(lp);
    if (lane < EN) { g_p[row * EN + lane] = p; g_lp[row * EN + lane] = lp; }

    float av  = (lane < EN) ? p * lp : 0.f;
    float evv = (lane < EN && r < 0.1f) ? r : 0.f;
    float nv  = (lane < EN) ? r * logf(r + 1e-8f) : 0.f;
#pragma unroll
    for (int o = 4; o > 0; o >>= 1) {
        av  += __shfl_xor_sync(0xffffffffu, av, o);
        evv += __shfl_xor_sync(0xffffffffu, evv, o);
        nv  += __shfl_xor_sync(0xffffffffu, nv, o);
    }
    if (lane < EN) atomicAdd(&s_us[lane], r);
    if (lane == 0) {
        g_a[row] = av;
        float l0 = logits[row * 3 + 0], l1 = logits[row * 3 + 1], l2 = logits[row * 3 + 2];
        float mm = fmaxf(l0, fmaxf(l1, l2));
        float lsm = mm + logf(expf(l0 - mm) + expf(l1 - mm) + expf(l2 - mm));
        int t = targets[row];
        float lt = (t == 0) ? l0 : ((t == 1) ? l1 : l2);
        s_task[warp] = (double)(lsm - lt);
        s_eff[warp]  = (double)evv;
        s_ent[warp]  = (double)nv;
    }
    __syncthreads();
    if (threadIdx.x == 0) {
        double a = 0, b = 0, c = 0;
        for (int i = 0; i < 8; i++) { a += s_task[i]; b += s_eff[i]; c += s_ent[i]; }
        g_pp_task[blockIdx.x] = a;
        g_pp_eff[blockIdx.x]  = b;
        g_pp_ent[blockIdx.x]  = c;
    }
    if (threadIdx.x < EN) g_pp_us[blockIdx.x * EN + threadIdx.x] = s_us[threadIdx.x];
}

// ---------------- HMMA pair kernel with cp.async pipeline -------------------
// Persistent 296 CTAs. K in 4 chunks of 32; double-buffered cp.async stages
// (chunk c lives in stage (c+1)&1; issue target for chunk c+1 is stage c&1).
// Cross-tile: next tile's chunk0 prefetched during chunk3's MMA + epilogue.
// Last CTA (ticket) reduces all partials and writes the final loss.
__global__ __launch_bounds__(256, 2) void pair_kernel(
    const float* __restrict__ temperature, float* __restrict__ out) {
    __shared__ __align__(1024) unsigned char sbuf[2][2][TS * 64];  // 32 KB
    __shared__ float sIa[TS], sJa[TS];
    __shared__ float s_rk[8];
    __shared__ int   s_rc[8];
    __shared__ double s_fin[6][8];   // K, C, task, eff, ent, usage
    __shared__ int s_last;

    int tid  = threadIdx.x;
    int wid  = tid >> 5;
    int lane = tid & 31;

    unsigned sbA[2] = { smem_u32(sbuf[0][0]), smem_u32(sbuf[1][0]) };
    unsigned sbB[2] = { smem_u32(sbuf[0][1]), smem_u32(sbuf[1][1]) };

    // epilogue aliases: stage0 holds p/logp after GEMM of current tile
    float* sPi  = (float*)sbuf[0][0];                    // 4 KB
    float* sLPi = (float*)(sbuf[0][0] + 4096);
    float* sPj  = (float*)sbuf[0][1];
    float* sLPj = (float*)(sbuf[0][1] + 4096);

    int mbase = (wid & 3) * 32;
    int nbase = (wid >> 2) * 64;
    int rowA  = ((lane >> 3) & 1) * 8 + (lane & 7);
    int qselA = lane >> 4;
    int rowB  = ((lane >> 4) & 1) * 8 + (lane & 7);
    int qselB = (lane >> 3) & 1;

    float kls = 0.f;
    int   cnt = 0;

    // decode first tile + prefetch its chunk0 into stage1
    int ti = 0, rem = blockIdx.x;
    while (rem >= NT - ti) { rem -= NT - ti; ti++; }
    int tj = ti + rem;
    {
#pragma unroll
        for (int rr = 0; rr < 2; rr++) {
            unsigned off = (unsigned)(tid + rr * 256) * 16;
            cpa16(sbA[1] + off, g_ct[0][ti] + off);
            cpa16(sbB[1] + off, g_ct[0][tj] + off);
        }
        CP_COMMIT();
    }

    for (int t = blockIdx.x; t < NPAIR; t += GRID_PAIR) {
        bool diag = (ti == tj);
        int ibase = ti * TS, jbase = tj * TS;

        // decode next tile (for cross-tile prefetch); self if none
        int tn = t + GRID_PAIR;
        int ti2, tj2;
        if (tn < NPAIR) {
            int a = 0, r2 = tn;
            while (r2 >= NT - a) { r2 -= NT - a; a++; }
            ti2 = a; tj2 = a + r2;
        } else { ti2 = ti; tj2 = tj; }

        float acc[2][8][4];
#pragma unroll
        for (int a = 0; a < 2; a++)
#pragma unroll
            for (int b = 0; b < 8; b++)
#pragma unroll
                for (int c = 0; c < 4; c++) acc[a][b][c] = 0.f;

#pragma unroll
        for (int c = 0; c < 4; c++) {
            __syncthreads();            // prior reads of issue-target stage done
            {
                int  nc = (c + 1) & 3;                 // chunk to fetch
                int  fa = (c < 3) ? ti : ti2;
                int  fb = (c < 3) ? tj : tj2;
                int  st = c & 1;                       // issue target stage
#pragma unroll
                for (int rr = 0; rr < 2; rr++) {
                    unsigned off = (unsigned)(tid + rr * 256) * 16;
                    cpa16(sbA[st] + off, g_ct[nc][fa] + off);
                    cpa16(sbB[st] + off, g_ct[nc][fb] + off);
                }
                CP_COMMIT();
            }
            CP_WAIT1();                 // chunk c landed
            __syncthreads();

            int s = (c + 1) & 1;        // stage holding chunk c
            unsigned aU = sbA[s], bU = sbB[s];
#pragma unroll
            for (int s16 = 0; s16 < 2; s16++) {
                unsigned af[2][4], bf[4][4];
#pragma unroll
                for (int mt = 0; mt < 2; mt++) {
                    int r = mbase + mt * 16 + rowA;
                    ldsm4(af[mt], aU + coff(r, s16 * 2 + qselA));
                }
#pragma unroll
                for (int pnt = 0; pnt < 4; pnt++) {
                    int r = nbase + pnt * 16 + rowB;
                    ldsm4(bf[pnt], bU + coff(r, s16 * 2 + qselB));
                }
#pragma unroll
                for (int mt = 0; mt < 2; mt++)
#pragma unroll
                    for (int pnt = 0; pnt < 4; pnt++) {
                        mma16816(acc[mt][pnt * 2 + 0], af[mt], &bf[pnt][0]);
                        mma16816(acc[mt][pnt * 2 + 1], af[mt], &bf[pnt][2]);
                    }
            }
        }

        // ---- stage p / logp / a into stage0 (chunk3 dead after sync) ----
        __syncthreads();
        for (int idx = tid; idx < (TS * EN) / 4; idx += 256) {
            ((float4*)sPi)[idx]  = ((const float4*)(g_p  + ibase * EN))[idx];
            ((float4*)sLPi)[idx] = ((const float4*)(g_lp + ibase * EN))[idx];
            ((float4*)sPj)[idx]  = ((const float4*)(g_p  + jbase * EN))[idx];
            ((float4*)sLPj)[idx] = ((const float4*)(g_lp + jbase * EN))[idx];
        }
        if (tid < TS) { sIa[tid] = g_a[ibase + tid]; sJa[tid] = g_a[jbase + tid]; }
        __syncthreads();

        // ---- masked KL epilogue ----
#pragma unroll
        for (int mt = 0; mt < 2; mt++) {
#pragma unroll
            for (int hf = 0; hf < 2; hf++) {
                int il = mbase + mt * 16 + hf * 8 + (lane >> 2);
                float4 pi0  = *(const float4*)(sPi  + il * EN);
                float4 pi1  = *(const float4*)(sPi  + il * EN + 4);
                float4 lpi0 = *(const float4*)(sLPi + il * EN);
                float4 lpi1 = *(const float4*)(sLPi + il * EN + 4);
                float  a_i  = sIa[il];
#pragma unroll
                for (int nt = 0; nt < 8; nt++) {
                    float v0 = acc[mt][nt][hf * 2 + 0];
                    float v1 = acc[mt][nt][hf * 2 + 1];
                    if (!(v0 > 0.8f) && !(v1 > 0.8f)) continue;
                    int jl0 = nbase + nt * 8 + (lane & 3) * 2;
#pragma unroll
                    for (int cc = 0; cc < 2; cc++) {
                        float f = (cc == 0) ? v0 : v1;
                        int jl = jl0 + cc;
                        if (f > 0.8f && !(diag && il == jl)) {
                            float4 pj0 = *(const float4*)(sPj + jl * EN);
                            float4 pj1 = *(const float4*)(sPj + jl * EN + 4);
                            float d1 = lpi0.x * pj0.x + lpi0.y * pj0.y +
                                       lpi0.z * pj0.z + lpi0.w * pj0.w +
                                       lpi1.x * pj1.x + lpi1.y * pj1.y +
                                       lpi1.z * pj1.z + lpi1.w * pj1.w;
                            float kl1 = sJa[jl] - d1;
                            if (diag) {
                                kls += kl1; cnt += 1;
                            } else {
                                float4 lpj0 = *(const float4*)(sLPj + jl * EN);
                                float4 lpj1 = *(const float4*)(sLPj + jl * EN + 4);
                                float d2 = lpj0.x * pi0.x + lpj0.y * pi0.y +
                                           lpj0.z * pi0.z + lpj0.w * pi0.w +
                                           lpj1.x * pi1.x + lpj1.y * pi1.y +
                                           lpj1.z * pi1.z + lpj1.w * pi1.w;
                                kls += kl1 + (a_i - d2); cnt += 2;
                            }
                        }
                    }
                }
            }
        }
        ti = ti2; tj = tj2;
    }
    CP_WAIT0();   // drain the final (self) prefetch

    // ---- flush per-CTA partial ----
#pragma unroll
    for (int o = 16; o > 0; o >>= 1) {
        kls += __shfl_xor_sync(0xffffffffu, kls, o);
        cnt += __shfl_xor_sync(0xffffffffu, cnt, o);
    }
    if (lane == 0) { s_rk[wid] = kls; s_rc[wid] = cnt; }
    __syncthreads();
    if (tid == 0) {
        double K = 0, C = 0;
        for (int w = 0; w < 8; w++) { K += (double)s_rk[w]; C += (double)s_rc[w]; }
        g_pair_kl[blockIdx.x]  = K;
        g_pair_cnt[blockIdx.x] = C;
        __threadfence();
        unsigned old = atomicAdd(&g_ticket, 1u);
        s_last = ((old % GRID_PAIR) == GRID_PAIR - 1) ? 1 : 0;
    }
    __syncthreads();
    if (!s_last) return;
    __threadfence();

    // ---- last CTA: reduce all partials, compute final loss ----
    double K = 0, C = 0, Tk = 0, Ef = 0, Ent = 0;
    for (int i = tid; i < GRID_PAIR; i += 256) { K += g_pair_kl[i]; C += g_pair_cnt[i]; }
    for (int i = tid; i < PREP_BLKS; i += 256) {
        Tk += g_pp_task[i]; Ef += g_pp_eff[i]; Ent += g_pp_ent[i];
    }
    double Us = 0;                     // warp w reduces expert w
    for (int i = lane; i < PREP_BLKS; i += 32) Us += (double)g_pp_us[i * EN + wid];

    K = wredd(K); C = wredd(C); Tk = wredd(Tk); Ef = wredd(Ef); Ent = wredd(Ent);
    Us = wredd(Us);
    if (lane == 0) {
        s_fin[0][wid] = K;  s_fin[1][wid] = C;  s_fin[2][wid] = Tk;
        s_fin[3][wid] = Ef; s_fin[4][wid] = Ent; s_fin[5][wid] = Us;
    }
    __syncthreads();
    if (tid == 0) {
        double k = 0, c = 0, tk = 0, ef = 0, en = 0;
        for (int w = 0; w < 8; w++) {
            k += s_fin[0][w]; c += s_fin[1][w]; tk += s_fin[2][w];
            ef += s_fin[3][w]; en += s_fin[4][w];
        }
        double u[EN], mu = 0.0;
        for (int e = 0; e < EN; e++) { u[e] = s_fin[5][e] / (double)BN; mu += u[e]; }
        mu /= (double)EN;
        double var = 0.0;
        for (int e = 0; e < EN; e++) var += (u[e] - mu) * (u[e] - mu);
        var /= (double)(EN - 1);
        double cons = (c > 0.0) ? 0.1 * (k / c) : 0.0;
        double tt = (double)temperature[0] - 1.0;
        double loss = tk / (double)BN
                    + 0.1 * var * (double)(EN * EN)
                    + 0.05 * ef / (double)BN
                    + cons
                    + 0.01 * en / (double)BN
                    + 0.01 * tt * tt;
        out[0] = (float)loss;
    }
}

// ---------------- launch -----------------------------------------------------
extern "C" void kernel_launch(void* const* d_in, const int* in_sizes, int n_in,
                              void* d_out, int out_size) {
    const float* logits  = (const float*)d_in[0];
    const int*   targets = (const int*)d_in[1];
    const float* rp      = (const float*)d_in[2];
    const float* emb     = (const float*)d_in[3];
    const float* temp    = (const float*)d_in[4];
    float* out = (float*)d_out;

    prep_kernel<<<PREP_BLKS, 256>>>(logits, targets, rp, emb);
    pair_kernel<<<GRID_PAIR, 256>>>(temp, out);
}

// round 8
// speedup vs baseline: 1.6056x; 1.6056x over previous
#include <cuda_runtime.h>
#include <cuda_bf16.h>

#define BN 8192
#define EN 8
#define HN 128
#define TS 128
#define NT (BN / TS)                 // 64 tiles per dim
#define NPAIR (NT * (NT + 1) / 2)    // 2080 upper-triangular tile pairs
#define GRID_PAIR 296                // 2 CTAs/SM, one wave
#define PREP_BLKS (BN / 8)           // 1024

// dynamic smem layout (bytes)
#define SM_STAGE   16384             // 8KB A + 8KB B per stage
#define SM_STAGES  (3 * SM_STAGE)    // 49152
#define SM_PI      (SM_STAGES)
#define SM_LPI     (SM_PI  + 4096)
#define SM_PJ      (SM_LPI + 4096)
#define SM_LPJ     (SM_PJ  + 4096)
#define SM_IA      (SM_LPJ + 4096)
#define SM_JA      (SM_IA  + 512)
#define SM_TOTAL   (SM_JA  + 512)    // 66560

// ---------------- device scratch -------------------------------------------
// bf16 tile images in 4 K-chunks of 32. Chunk layout: 128 rows x 64B, packed
// two rows per 128B line, 16B-chunk swizzle:
//   byte(r,q) = (r>>1)*128 + (((r&1)*4) | (q ^ ((r>>1)&3)))*16,  q in 0..3
__device__ __align__(1024) unsigned char g_ct[4][NT][TS * 64];  // 2 MB
__device__ __align__(16) float g_p[BN * EN];
__device__ __align__(16) float g_lp[BN * EN];
__device__ __align__(16) float g_a[BN];
// prep per-block partials (written unconditionally -> no zeroing kernel)
__device__ double g_pp_task[PREP_BLKS], g_pp_eff[PREP_BLKS], g_pp_ent[PREP_BLKS];
__device__ float  g_pp_us[PREP_BLKS * EN];
// pair per-CTA partials + never-reset ticket (modular check is replay-safe)
__device__ double g_pair_kl[GRID_PAIR];
__device__ double g_pair_cnt[GRID_PAIR];
__device__ unsigned g_ticket;

// ---------------- PTX helpers ----------------------------------------------
__device__ __forceinline__ unsigned smem_u32(const void* p) {
    unsigned a;
    asm("{ .reg .u64 t; cvta.to.shared.u64 t, %1; cvt.u32.u64 %0, t; }"
        : "=r"(a) : "l"(p));
    return a;
}
__device__ __forceinline__ void ldsm4(unsigned* r, unsigned addr) {
    asm volatile("ldmatrix.sync.aligned.m8n8.x4.shared.b16 {%0,%1,%2,%3}, [%4];"
                 : "=r"(r[0]), "=r"(r[1]), "=r"(r[2]), "=r"(r[3]) : "r"(addr));
}
__device__ __forceinline__ void mma16816(float* d, const unsigned* a, const unsigned* b) {
    asm volatile(
        "mma.sync.aligned.m16n8k16.row.col.f32.bf16.bf16.f32 "
        "{%0,%1,%2,%3}, {%4,%5,%6,%7}, {%8,%9}, {%0,%1,%2,%3};"
        : "+f"(d[0]), "+f"(d[1]), "+f"(d[2]), "+f"(d[3])
        : "r"(a[0]), "r"(a[1]), "r"(a[2]), "r"(a[3]), "r"(b[0]), "r"(b[1]));
}
__device__ __forceinline__ void cpa16(unsigned dst, const void* src) {
    asm volatile("cp.async.cg.shared.global [%0], [%1], 16;"
                 :: "r"(dst), "l"(src) : "memory");
}
#define CP_COMMIT() asm volatile("cp.async.commit_group;" ::: "memory")
#define CP_WAIT1()  asm volatile("cp.async.wait_group 1;" ::: "memory")
#define CP_WAIT0()  asm volatile("cp.async.wait_group 0;" ::: "memory")

// swizzled byte offset within a K-chunk tile
__device__ __forceinline__ unsigned coff(int r, int q) {
    return ((unsigned)(r >> 1) << 7) +
           ((((unsigned)(r & 1) << 2) | ((unsigned)q ^ ((unsigned)(r >> 1) & 3))) << 4);
}
__device__ __forceinline__ double wredd(double v) {
#pragma unroll
    for (int o = 16; o > 0; o >>= 1) v += __shfl_xor_sync(0xffffffffu, v, o);
    return v;
}

// ---------------- per-row preprocessing + cheap loss partials ---------------
__global__ __launch_bounds__(256) void prep_kernel(
    const float* __restrict__ logits,
    const int* __restrict__ targets,
    const float* __restrict__ rp,
    const float* __restrict__ emb) {
    int warp = threadIdx.x >> 5, lane = threadIdx.x & 31;
    int row = blockIdx.x * 8 + warp;
    __shared__ float  s_us[EN];
    __shared__ double s_task[8], s_eff[8], s_ent[8];
    if (threadIdx.x < EN) s_us[threadIdx.x] = 0.f;
    __syncthreads();

    // normalize embedding row (float4 per lane = 4 consecutive k-cols)
    float4 v = *(const float4*)(emb + (size_t)row * HN + lane * 4);
    float ss = v.x * v.x + v.y * v.y + v.z * v.z + v.w * v.w;
#pragma unroll
    for (int o = 16; o > 0; o >>= 1) ss += __shfl_xor_sync(0xffffffffu, ss, o);
    float inv = rsqrtf(ss);
    float4 w = make_float4(v.x * inv, v.y * inv, v.z * inv, v.w * inv);

    // store bf16 into chunked swizzled tile image
    {
        int cc = lane >> 3;                  // K-chunk 0..3
        int q  = (lane & 7) >> 1;            // 16B chunk in row
        int lr = row & (TS - 1);
        unsigned off = coff(lr, q) + (unsigned)(lane & 1) * 8;
        unsigned u0 = __bfloat16_as_ushort(__float2bfloat16_rn(w.x));
        unsigned u1 = __bfloat16_as_ushort(__float2bfloat16_rn(w.y));
        unsigned u2 = __bfloat16_as_ushort(__float2bfloat16_rn(w.z));
        unsigned u3 = __bfloat16_as_ushort(__float2bfloat16_rn(w.w));
        uint2 val = make_uint2(u0 | (u1 << 16), u2 | (u3 << 16));
        *(uint2*)(&g_ct[cc][row >> 7][off]) = val;
    }

    // routing-prob softmax over E=8
    float r = (lane < EN) ? rp[row * EN + lane] : -3.0e38f;
    float m = r;
#pragma unroll
    for (int o = 4; o > 0; o >>= 1) m = fmaxf(m, __shfl_xor_sync(0xffffffffu, m, o));
    float ex = (lane < EN) ? expf(r - m) : 0.f;
    float es = ex;
#pragma unroll
    for (int o = 4; o > 0; o >>= 1) es += __shfl_xor_sync(0xffffffffu, es, o);
    float lse = m + logf(es);
    float lp = r - lse;
    float p  = expf(lp);
    if (lane < EN) { g_p[row * EN + lane] = p; g_lp[row * EN + lane] = lp; }

    float av  = (lane < EN) ? p * lp : 0.f;
    float evv = (lane < EN && r < 0.1f) ? r : 0.f;
    float nv  = (lane < EN) ? r * logf(r + 1e-8f) : 0.f;
#pragma unroll
    for (int o = 4; o > 0; o >>= 1) {
        av  += __shfl_xor_sync(0xffffffffu, av, o);
        evv += __shfl_xor_sync(0xffffffffu, evv, o);
        nv  += __shfl_xor_sync(0xffffffffu, nv, o);
    }
    if (lane < EN) atomicAdd(&s_us[lane], r);
    if (lane == 0) {
        g_a[row] = av;
        float l0 = logits[row * 3 + 0], l1 = logits[row * 3 + 1], l2 = logits[row * 3 + 2];
        float mm = fmaxf(l0, fmaxf(l1, l2));
        float lsm = mm + logf(expf(l0 - mm) + expf(l1 - mm) + expf(l2 - mm));
        int t = targets[row];
        float lt = (t == 0) ? l0 : ((t == 1) ? l1 : l2);
        s_task[warp] = (double)(lsm - lt);
        s_eff[warp]  = (double)evv;
        s_ent[warp]  = (double)nv;
    }
    __syncthreads();
    if (threadIdx.x == 0) {
        double a = 0, b = 0, c = 0;
        for (int i = 0; i < 8; i++) { a += s_task[i]; b += s_eff[i]; c += s_ent[i]; }
        g_pp_task[blockIdx.x] = a;
        g_pp_eff[blockIdx.x]  = b;
        g_pp_ent[blockIdx.x]  = c;
    }
    if (threadIdx.x < EN) g_pp_us[blockIdx.x * EN + threadIdx.x] = s_us[threadIdx.x];
}

// ---------------- HMMA pair kernel: 3-stage flat cp.async pipeline ----------
// Chunk stream across tiles; consume stage st, issue 2 chunks ahead into
// (st+2)%3, wait_group 1, ONE barrier per chunk. Epilogue p/lp/a prefetched
// via cp.async bundled with the tile's chunk-3 group (c=1 issue). Empty
// commit_groups at the tail keep wait_group counting exact.
__global__ __launch_bounds__(256, 2) void pair_kernel(
    const float* __restrict__ temperature, float* __restrict__ out) {
    extern __shared__ __align__(1024) unsigned char dsm[];
    __shared__ float s_rk[8];
    __shared__ int   s_rc[8];
    __shared__ double s_fin[6][8];
    __shared__ int s_last;

    int tid  = threadIdx.x;
    int wid  = tid >> 5;
    int lane = tid & 31;

    unsigned dbase = smem_u32(dsm);
    unsigned stA[3], stB[3];
#pragma unroll
    for (int s = 0; s < 3; s++) { stA[s] = dbase + s * SM_STAGE; stB[s] = stA[s] + 8192; }
    float* sPi  = (float*)(dsm + SM_PI);
    float* sLPi = (float*)(dsm + SM_LPI);
    float* sPj  = (float*)(dsm + SM_PJ);
    float* sLPj = (float*)(dsm + SM_LPJ);
    float* sIa  = (float*)(dsm + SM_IA);
    float* sJa  = (float*)(dsm + SM_JA);
    unsigned uPi = dbase + SM_PI, uLPi = dbase + SM_LPI;
    unsigned uPj = dbase + SM_PJ, uLPj = dbase + SM_LPJ;
    unsigned uIa = dbase + SM_IA, uJa = dbase + SM_JA;

    int mbase = (wid & 3) * 32;
    int nbase = (wid >> 2) * 64;
    int rowA  = ((lane >> 3) & 1) * 8 + (lane & 7);
    int qselA = lane >> 4;
    int rowB  = ((lane >> 4) & 1) * 8 + (lane & 7);
    int qselB = (lane >> 3) & 1;

    // precompute per-lane ldmatrix offsets (constant across chunks/stages)
    unsigned offA[2][2], offB[4][2];
#pragma unroll
    for (int mt = 0; mt < 2; mt++)
#pragma unroll
        for (int s16 = 0; s16 < 2; s16++)
            offA[mt][s16] = coff(mbase + mt * 16 + rowA, s16 * 2 + qselA);
#pragma unroll
    for (int pnt = 0; pnt < 4; pnt++)
#pragma unroll
        for (int s16 = 0; s16 < 2; s16++)
            offB[pnt][s16] = coff(nbase + pnt * 16 + rowB, s16 * 2 + qselB);

    unsigned co0 = (unsigned)tid * 16u;     // thread's copy slots
    unsigned co1 = co0 + 4096u;

    float kls = 0.f;
    int   cnt = 0;

    // decode first tile
    int ti = 0, rem = blockIdx.x;
    while (rem >= NT - ti) { rem -= NT - ti; ti++; }
    int tj = ti + rem;

    // prologue: chunk0 -> stage0, chunk1 -> stage1
#pragma unroll
    for (int c = 0; c < 2; c++) {
        cpa16(stA[c] + co0, g_ct[c][ti] + co0);
        cpa16(stA[c] + co1, g_ct[c][ti] + co1);
        cpa16(stB[c] + co0, g_ct[c][tj] + co0);
        cpa16(stB[c] + co1, g_ct[c][tj] + co1);
        CP_COMMIT();
    }

    int st = 0;
    for (int t = blockIdx.x; t < NPAIR; t += GRID_PAIR) {
        bool diag = (ti == tj);
        int ibase = ti * TS, jbase = tj * TS;
        int ti2 = ti, tj2 = tj;
        bool more = (t + GRID_PAIR) < NPAIR;
        if (more) {
            int a = 0, r2 = t + GRID_PAIR;
            while (r2 >= NT - a) { r2 -= NT - a; a++; }
            ti2 = a; tj2 = a + r2;
        }

        float acc[2][8][4];
#pragma unroll
        for (int a = 0; a < 2; a++)
#pragma unroll
            for (int b = 0; b < 8; b++)
#pragma unroll
                for (int c = 0; c < 4; c++) acc[a][b][c] = 0.f;

#pragma unroll
        for (int c = 0; c < 4; c++) {
            CP_WAIT1();
            __syncthreads();
            // issue 2 chunks ahead into stage (st+2)%3
            {
                int tgt = st + 2; if (tgt >= 3) tgt -= 3;
                if (c < 2) {                       // chunks 2,3 of current tile
                    int nc = c + 2;
                    cpa16(stA[tgt] + co0, g_ct[nc][ti] + co0);
                    cpa16(stA[tgt] + co1, g_ct[nc][ti] + co1);
                    cpa16(stB[tgt] + co0, g_ct[nc][tj] + co0);
                    cpa16(stB[tgt] + co1, g_ct[nc][tj] + co1);
                    if (c == 1) {                  // epilogue bundle for THIS tile
                        cpa16(uPi  + co0, (const unsigned char*)(g_p  + ibase * EN) + co0);
                        cpa16(uLPi + co0, (const unsigned char*)(g_lp + ibase * EN) + co0);
                        cpa16(uPj  + co0, (const unsigned char*)(g_p  + jbase * EN) + co0);
                        cpa16(uLPj + co0, (const unsigned char*)(g_lp + jbase * EN) + co0);
                        if (tid < 32) {
                            cpa16(uIa + co0, (const unsigned char*)(g_a + ibase) + co0);
                            cpa16(uJa + co0, (const unsigned char*)(g_a + jbase) + co0);
                        }
                    }
                } else if (more) {                 // chunks 0,1 of next tile
                    int nc = c - 2;
                    cpa16(stA[tgt] + co0, g_ct[nc][ti2] + co0);
                    cpa16(stA[tgt] + co1, g_ct[nc][ti2] + co1);
                    cpa16(stB[tgt] + co0, g_ct[nc][tj2] + co0);
                    cpa16(stB[tgt] + co1, g_ct[nc][tj2] + co1);
                }
                CP_COMMIT();                       // always (empty groups at tail)
            }

            // MMA on chunk c from stage st
            unsigned aU = stA[st], bU = stB[st];
#pragma unroll
            for (int s16 = 0; s16 < 2; s16++) {
                unsigned af[2][4], bf[4][4];
#pragma unroll
                for (int mt = 0; mt < 2; mt++) ldsm4(af[mt], aU + offA[mt][s16]);
#pragma unroll
                for (int pnt = 0; pnt < 4; pnt++) ldsm4(bf[pnt], bU + offB[pnt][s16]);
#pragma unroll
                for (int mt = 0; mt < 2; mt++)
#pragma unroll
                    for (int pnt = 0; pnt < 4; pnt++) {
                        mma16816(acc[mt][pnt * 2 + 0], af[mt], &bf[pnt][0]);
                        mma16816(acc[mt][pnt * 2 + 1], af[mt], &bf[pnt][2]);
                    }
            }
            st = st + 1; if (st >= 3) st -= 3;
        }

        // ---- masked KL epilogue (operands already in smem via bundle) ----
#pragma unroll
        for (int mt = 0; mt < 2; mt++) {
#pragma unroll
            for (int hf = 0; hf < 2; hf++) {
                int il = mbase + mt * 16 + hf * 8 + (lane >> 2);
                float4 pi0  = *(const float4*)(sPi  + il * EN);
                float4 pi1  = *(const float4*)(sPi  + il * EN + 4);
                float4 lpi0 = *(const float4*)(sLPi + il * EN);
                float4 lpi1 = *(const float4*)(sLPi + il * EN + 4);
                float  a_i  = sIa[il];
#pragma unroll
                for (int nt = 0; nt < 8; nt++) {
                    float v0 = acc[mt][nt][hf * 2 + 0];
                    float v1 = acc[mt][nt][hf * 2 + 1];
                    if (!(v0 > 0.8f) && !(v1 > 0.8f)) continue;
                    int jl0 = nbase + nt * 8 + (lane & 3) * 2;
#pragma unroll
                    for (int cc = 0; cc < 2; cc++) {
                        float f = (cc == 0) ? v0 : v1;
                        int jl = jl0 + cc;
                        if (f > 0.8f && !(diag && il == jl)) {
                            float4 pj0 = *(const float4*)(sPj + jl * EN);
                            float4 pj1 = *(const float4*)(sPj + jl * EN + 4);
                            float d1 = lpi0.x * pj0.x + lpi0.y * pj0.y +
                                       lpi0.z * pj0.z + lpi0.w * pj0.w +
                                       lpi1.x * pj1.x + lpi1.y * pj1.y +
                                       lpi1.z * pj1.z + lpi1.w * pj1.w;
                            float kl1 = sJa[jl] - d1;
                            if (diag) {
                                kls += kl1; cnt += 1;
                            } else {
                                float4 lpj0 = *(const float4*)(sLPj + jl * EN);
                                float4 lpj1 = *(const float4*)(sLPj + jl * EN + 4);
                                float d2 = lpj0.x * pi0.x + lpj0.y * pi0.y +
                                           lpj0.z * pi0.z + lpj0.w * pi0.w +
                                           lpj1.x * pi1.x + lpj1.y * pi1.y +
                                           lpj1.z * pi1.z + lpj1.w * pi1.w;
                                kls += kl1 + (a_i - d2); cnt += 2;
                            }
                        }
                    }
                }
            }
        }
        ti = ti2; tj = tj2;
    }
    CP_WAIT0();

    // ---- flush per-CTA partial ----
#pragma unroll
    for (int o = 16; o > 0; o >>= 1) {
        kls += __shfl_xor_sync(0xffffffffu, kls, o);
        cnt += __shfl_xor_sync(0xffffffffu, cnt, o);
    }
    if (lane == 0) { s_rk[wid] = kls; s_rc[wid] = cnt; }
    __syncthreads();
    if (tid == 0) {
        double K = 0, C = 0;
        for (int w = 0; w < 8; w++) { K += (double)s_rk[w]; C += (double)s_rc[w]; }
        g_pair_kl[blockIdx.x]  = K;
        g_pair_cnt[blockIdx.x] = C;
        __threadfence();
        unsigned old = atomicAdd(&g_ticket, 1u);
        s_last = ((old % GRID_PAIR) == GRID_PAIR - 1) ? 1 : 0;
    }
    __syncthreads();
    if (!s_last) return;
    __threadfence();

    // ---- last CTA: reduce all partials, compute final loss ----
    double K = 0, C = 0, Tk = 0, Ef = 0, Ent = 0;
    for (int i = tid; i < GRID_PAIR; i += 256) { K += g_pair_kl[i]; C += g_pair_cnt[i]; }
    for (int i = tid; i < PREP_BLKS; i += 256) {
        Tk += g_pp_task[i]; Ef += g_pp_eff[i]; Ent += g_pp_ent[i];
    }
    double Us = 0;                     // warp w reduces expert w
    for (int i = lane; i < PREP_BLKS; i += 32) Us += (double)g_pp_us[i * EN + wid];

    K = wredd(K); C = wredd(C); Tk = wredd(Tk); Ef = wredd(Ef); Ent = wredd(Ent);
    Us = wredd(Us);
    if (lane == 0) {
        s_fin[0][wid] = K;  s_fin[1][wid] = C;  s_fin[2][wid] = Tk;
        s_fin[3][wid] = Ef; s_fin[4][wid] = Ent; s_fin[5][wid] = Us;
    }
    __syncthreads();
    if (tid == 0) {
        double k = 0, c = 0, tk = 0, ef = 0, en = 0;
        for (int w = 0; w < 8; w++) {
            k += s_fin[0][w]; c += s_fin[1][w]; tk += s_fin[2][w];
            ef += s_fin[3][w]; en += s_fin[4][w];
        }
        double u[EN], mu = 0.0;
        for (int e = 0; e < EN; e++) { u[e] = s_fin[5][e] / (double)BN; mu += u[e]; }
        mu /= (double)EN;
        double var = 0.0;
        for (int e = 0; e < EN; e++) var += (u[e] - mu) * (u[e] - mu);
        var /= (double)(EN - 1);
        double cons = (c > 0.0) ? 0.1 * (k / c) : 0.0;
        double tt = (double)temperature[0] - 1.0;
        double loss = tk / (double)BN
                    + 0.1 * var * (double)(EN * EN)
                    + 0.05 * ef / (double)BN
                    + cons
                    + 0.01 * en / (double)BN
                    + 0.01 * tt * tt;
        out[0] = (float)loss;
    }
}

// ---------------- launch -----------------------------------------------------
extern "C" void kernel_launch(void* const* d_in, const int* in_sizes, int n_in,
                              void* d_out, int out_size) {
    const float* logits  = (const float*)d_in[0];
    const int*   targets = (const int*)d_in[1];
    const float* rp      = (const float*)d_in[2];
    const float* emb     = (const float*)d_in[3];
    const float* temp    = (const float*)d_in[4];
    float* out = (float*)d_out;

    static int s_attr_done = 0;
    if (!s_attr_done) {
        cudaFuncSetAttribute(pair_kernel,
                             cudaFuncAttributeMaxDynamicSharedMemorySize, SM_TOTAL);
        s_attr_done = 1;
    }

    prep_kernel<<<PREP_BLKS, 256>>>(logits, targets, rp, emb);
    pair_kernel<<<GRID_PAIR, 256, SM_TOTAL>>>(temp, out);
}